// round 12
// baseline (speedup 1.0000x reference)
#include <cuda_runtime.h>
#include <cuda_bf16.h>

// Problem constants (match reference; runtime sizes derived from in_sizes)
#define NMAX   50000
#define EMAX   800000
#define HID    64
#define INCH   16
#define GMAX   128

// ---------------- scratch (device globals; no allocation allowed) ----------
__device__ __align__(16) float g_dinv[NMAX];                 // degree -> deg^{-1/2}
__device__ __align__(16) float g_h   [(size_t)NMAX * HID];   // transformed features
__device__ __align__(16) float g_acc [(size_t)NMAX * HID];   // aggregation accumulator
__device__ __align__(16) float g_pool[GMAX * HID];
__device__ __align__(16) float g_cnt [GMAX];

// ---------------- helpers ---------------------------------------------------
__device__ __forceinline__ void red_add_f4(float* p, float4 v) {
    asm volatile("red.global.add.v4.f32 [%0], {%1,%2,%3,%4};"
                 :: "l"(p), "f"(v.x), "f"(v.y), "f"(v.z), "f"(v.w) : "memory");
}
__device__ __forceinline__ void red_add_f(float* p, float v) {
    asm volatile("red.global.add.f32 [%0], %1;" :: "l"(p), "f"(v) : "memory");
}

// ---------------- k0: init --------------------------------------------------
__global__ void k_init(int n) {
    int i = blockIdx.x * blockDim.x + threadIdx.x;
    if (i < n) g_dinv[i] = 1.0f;              // self-loop contributes 1 to degree
    if (i < GMAX * HID) g_pool[i] = 0.0f;
    if (i < GMAX) g_cnt[i] = 0.0f;
}

// ---------------- k1: in-degree scatter -------------------------------------
__global__ void k_deg(const int* __restrict__ dst, int e) {
    int i = blockIdx.x * blockDim.x + threadIdx.x;
    if (i < e) red_add_f(&g_dinv[dst[i]], 1.0f);
}

// ---------------- k2: dinv + h = x@W1 + acc = h*dinv^2 ----------------------
// 256 threads = 4 nodes x 64 channels
__global__ void k_lin1(const float* __restrict__ x, const float* __restrict__ W1, int n) {
    __shared__ float Ws[INCH * HID];   // 4 KB
    __shared__ float xs[4][INCH];
    __shared__ float ds[4];
    int tid = threadIdx.x;
    for (int i = tid; i < INCH * HID; i += 256) Ws[i] = W1[i];
    int node0 = blockIdx.x * 4;
    if (tid < 4 * INCH) {
        int nl = tid >> 4, k = tid & 15;
        int node = node0 + nl;
        xs[nl][k] = (node < n) ? x[(size_t)node * INCH + k] : 0.0f;
    }
    if (tid < 4) {
        int node = node0 + tid;
        ds[tid] = (node < n) ? rsqrtf(g_dinv[node]) : 0.0f;
    }
    __syncthreads();
    int nl = tid >> 6, ch = tid & 63;
    int node = node0 + nl;
    if (node < n) {
        float s = 0.0f;
        #pragma unroll
        for (int k = 0; k < INCH; k++) s += xs[nl][k] * Ws[k * HID + ch];
        float d = ds[nl];
        if (ch == 0) g_dinv[node] = d;          // overwrite deg with dinv
        g_h  [(size_t)node * HID + ch] = s;
        g_acc[(size_t)node * HID + ch] = s * d * d;   // self-loop message
    }
}

// ---------------- edge scatter: acc[d] += h[s]*dinv[s]*dinv[d] ---------------
// thread = (edge, float4 chunk); 16 chunks/edge; coalesced 256B per edge
__global__ void k_edge(const int* __restrict__ src,
                       const int* __restrict__ dst, int e) {
    int gid = blockIdx.x * blockDim.x + threadIdx.x;
    if (gid >= e * 16) return;
    int ei = gid >> 4;
    int c  = gid & 15;
    int s = __ldg(&src[ei]);
    int d = __ldg(&dst[ei]);
    float nrm = __ldg(&g_dinv[s]) * __ldg(&g_dinv[d]);
    float4 v = *reinterpret_cast<const float4*>(g_h + (size_t)s * HID + c * 4);
    v.x *= nrm; v.y *= nrm; v.z *= nrm; v.w *= nrm;
    red_add_f4(g_acc + (size_t)d * HID + c * 4, v);
}

// ---------------- k4: z = relu(acc+b1); h = z@W2; acc = h*dinv^2 -------------
__global__ void k_lin2(const float* __restrict__ W2, const float* __restrict__ b1, int n) {
    __shared__ float Ws[HID * HID];   // 16 KB
    __shared__ float zs[4][HID];
    int tid = threadIdx.x;
    for (int i = tid; i < HID * HID; i += 256) Ws[i] = W2[i];
    int node0 = blockIdx.x * 4;
    int nl = tid >> 6, ch = tid & 63;
    int node = node0 + nl;
    float z = 0.0f;
    if (node < n) z = fmaxf(g_acc[(size_t)node * HID + ch] + b1[ch], 0.0f);
    zs[nl][ch] = z;
    __syncthreads();
    if (node < n) {
        float s = 0.0f;
        #pragma unroll
        for (int k = 0; k < HID; k++) s += zs[nl][k] * Ws[k * HID + ch];
        float d = g_dinv[node];
        g_h  [(size_t)node * HID + ch] = s;
        g_acc[(size_t)node * HID + ch] = s * d * d;
    }
}

// ---------------- k6: pool per graph ----------------------------------------
__global__ void k_pool(const float* __restrict__ b2,
                       const int* __restrict__ batch, int n) {
    int gid = blockIdx.x * blockDim.x + threadIdx.x;
    if (gid >= n * 16) return;
    int node = gid >> 4;
    int c = gid & 15;
    int g = __ldg(&batch[node]);
    float4 v = *reinterpret_cast<const float4*>(g_acc + (size_t)node * HID + c * 4);
    v.x = fmaxf(v.x + b2[c * 4 + 0], 0.0f);
    v.y = fmaxf(v.y + b2[c * 4 + 1], 0.0f);
    v.z = fmaxf(v.z + b2[c * 4 + 2], 0.0f);
    v.w = fmaxf(v.w + b2[c * 4 + 3], 0.0f);
    red_add_f4(g_pool + g * HID + c * 4, v);
    if (c == 0) red_add_f(&g_cnt[g], 1.0f);
}

// ---------------- k7: classifier [G,64] @ [64,outc] + bc --------------------
__global__ void k_cls(const float* __restrict__ Wc, const float* __restrict__ bc,
                      float* __restrict__ out, int n_graphs, int outc) {
    int tid = blockIdx.x * blockDim.x + threadIdx.x;
    if (tid >= n_graphs * outc) return;
    int g = tid / outc, o = tid % outc;
    float cnt = fmaxf(g_cnt[g], 1.0f);
    float inv = 1.0f / cnt;
    float s = 0.0f;
    #pragma unroll
    for (int k = 0; k < HID; k++)
        s += g_pool[g * HID + k] * inv * Wc[k * outc + o];
    out[g * outc + o] = s + bc[o];
}

// ---------------- launch -----------------------------------------------------
extern "C" void kernel_launch(void* const* d_in, const int* in_sizes, int n_in,
                              void* d_out, int out_size) {
    const float* x   = (const float*)d_in[0];
    const int*   ei  = (const int*)d_in[1];     // [2, E] int32 (JAX x64 disabled)
    const int*   bat = (const int*)d_in[2];     // [N]    int32
    const float* W1  = (const float*)d_in[3];
    const float* b1  = (const float*)d_in[4];
    const float* W2  = (const float*)d_in[5];
    const float* b2  = (const float*)d_in[6];
    const float* Wc  = (const float*)d_in[7];
    const float* bc  = (const float*)d_in[8];
    float* out = (float*)d_out;

    int n = in_sizes[0] / INCH;        // 50000
    int e = in_sizes[1] / 2;           // 800000
    int outc = 2;
    int ngr = out_size / outc;         // 128

    const int* src = ei;
    const int* dst = ei + e;

    int init_elems = n > GMAX * HID ? n : GMAX * HID;
    k_init<<<(init_elems + 255) / 256, 256>>>(n);
    k_deg <<<(e + 255) / 256, 256>>>(dst, e);
    k_lin1<<<(n + 3) / 4, 256>>>(x, W1, n);
    k_edge<<<(e * 16 + 255) / 256, 256>>>(src, dst, e);
    k_lin2<<<(n + 3) / 4, 256>>>(W2, b1, n);
    k_edge<<<(e * 16 + 255) / 256, 256>>>(src, dst, e);
    k_pool<<<(n * 16 + 255) / 256, 256>>>(b2, bat, n);
    k_cls <<<(ngr * outc + 255) / 256, 256>>>(Wc, bc, out, ngr, outc);
}